// round 6
// baseline (speedup 1.0000x reference)
// CrossLayerTranscoder — tf32 mma.sync GEMM. R6: XOR fragment addressing +
// incremental row-per-thread cp.async loader to cut non-MMA instructions and
// register pressure (R5 was latency-bound at 246 regs, tensor 62.9%).
//
// encode: feats[l] = relu(resid[l] @ enc_w[l]^T)            M=2048,N=512,K=2048
// decode: recon[t] = sum_{s<=t} feats[s] @ dec_w[s,t]^T     M=2048,N=2048,K=(t+1)*512
//
// CTA 128x128x32, 3-stage cp.async, 128 threads (2 CTAs/SM), 4 warps of 64x64.

#include <cuda_runtime.h>
#include <cstdint>
#include <cstddef>

#define L_DIM 16
#define BS_DIM 2048
#define H_DIM 2048
#define F_DIM 512

#define TM 128
#define TN 128
#define TK 32
#define STAGES 3
#define NTHREADS 128

#define A_BYTES 16384                        // TM*TK*4
#define STAGE_BYTES 32768                    // A + B
#define SMEM_BYTES (STAGES * STAGE_BYTES)    // 96 KB

__device__ __forceinline__ uint32_t smem_u32(const void* p) {
    uint32_t a;
    asm("{ .reg .u64 t; cvta.to.shared.u64 t, %1; cvt.u32.u64 %0, t; }" : "=r"(a) : "l"(p));
    return a;
}
__device__ __forceinline__ void cp_async16(uint32_t dst, const float* src) {
    asm volatile("cp.async.cg.shared.global [%0], [%1], 16;" :: "r"(dst), "l"(src));
}
__device__ __forceinline__ void cp_commit() { asm volatile("cp.async.commit_group;"); }
template <int N> __device__ __forceinline__ void cp_wait() {
    asm volatile("cp.async.wait_group %0;" :: "n"(N));
}
__device__ __forceinline__ uint32_t ldtf32(uint32_t addr) {
    float v; uint32_t r;
    asm volatile("ld.shared.f32 %0, [%1];" : "=f"(v) : "r"(addr));
    asm("cvt.rna.tf32.f32 %0, %1;" : "=r"(r) : "f"(v));
    return r;
}
__device__ __forceinline__ void mma_tf32(float* c, const uint32_t* a, const uint32_t* b) {
    asm volatile(
        "mma.sync.aligned.m16n8k8.row.col.f32.tf32.tf32.f32 "
        "{%0,%1,%2,%3}, {%4,%5,%6,%7}, {%8,%9}, {%0,%1,%2,%3};"
        : "+f"(c[0]), "+f"(c[1]), "+f"(c[2]), "+f"(c[3])
        : "r"(a[0]), "r"(a[1]), "r"(a[2]), "r"(a[3]), "r"(b[0]), "r"(b[1]));
}

// SMEM tile layout: row-major 32 floats/row; chunk = (k>>2) ^ (row&7), word = k&3.
// For all fragment rows, row&7 == r8, so with rowbase = row*128 + (r8<<4) + t*4
// the address of (row, k=ks*8+t) is rowbase ^ ((2ks)<<4), and k+4 is that ^ 16.

template <bool ENCODE>
__global__ __launch_bounds__(NTHREADS, 2)
void clt_gemm(const float* __restrict__ gA, const float* __restrict__ gB,
              float* __restrict__ gOut) {
    extern __shared__ float smem[];
    const uint32_t sbase = smem_u32(smem);
    const int tid  = threadIdx.x;
    const int lane = tid & 31;
    const int w    = tid >> 5;
    const int wm   = w & 1;        // 2 warps along M (64 rows)
    const int wn   = w >> 1;       // 2 warps along N (64 cols)
    const int r8   = lane >> 2;
    const int t    = lane & 3;
    const int m0   = blockIdx.x * TM;
    const int n0   = blockIdx.y * TN;
    const int z    = (int)gridDim.z - 1 - (int)blockIdx.z;   // heavy z first
    const int iters = ENCODE ? (H_DIM / TK) : ((z + 1) * (F_DIM / TK));

    float acc[4][8][4];
    #pragma unroll
    for (int mt = 0; mt < 4; mt++)
        #pragma unroll
        for (int nt = 0; nt < 8; nt++)
            #pragma unroll
            for (int r = 0; r < 4; r++) acc[mt][nt][r] = 0.0f;

    // ---------- producer: thread owns A row tid and B row tid ----------
    const float* pA;
    const float* pB;
    if (ENCODE) {
        pA = gA + ((size_t)z * BS_DIM + m0 + tid) * H_DIM;
        pB = gB + ((size_t)z * F_DIM + n0 + tid) * H_DIM;
    } else {
        pA = gA + (size_t)(m0 + tid) * F_DIM;                      // feats[0] row
        pB = gB + ((size_t)z * H_DIM + n0 + tid) * F_DIM;          // dec_w[0][z] row
    }
    const uint32_t sw   = (uint32_t)((tid & 7) << 4);
    const uint32_t aRow = sbase + (uint32_t)tid * 128;
    int fi = 0;
    auto load_stage = [&]() {
        const int slot = fi % STAGES;   // fi%3: cheap, loop-carried by compiler
        uint32_t dA = aRow + (uint32_t)slot * STAGE_BYTES;
        uint32_t dB = dA + A_BYTES;
        #pragma unroll
        for (int c = 0; c < 8; c++)
            cp_async16(dA + (((uint32_t)(c << 4)) ^ sw), pA + c * 4);
        #pragma unroll
        for (int c = 0; c < 8; c++)
            cp_async16(dB + (((uint32_t)(c << 4)) ^ sw), pB + c * 4);
        cp_commit();
        if (ENCODE) { pA += TK; pB += TK; }
        else {
            bool roll = (fi & 15) == 15;   // next source layer s
            pA += roll ? ((size_t)BS_DIM * F_DIM - 15 * TK) : TK;
            pB += roll ? ((size_t)L_DIM * H_DIM * F_DIM - 15 * TK) : TK;
        }
        fi++;
    };

    // ---------- consumer rowbase offsets (bytes within tile) ----------
    uint32_t rbA[4][2], rbB[8];
    #pragma unroll
    for (int mt = 0; mt < 4; mt++) {
        int r = wm * 64 + mt * 16 + r8;
        rbA[mt][0] = (uint32_t)r * 128 + ((uint32_t)r8 << 4) + (uint32_t)t * 4;
        rbA[mt][1] = rbA[mt][0] + 8 * 128;
    }
    #pragma unroll
    for (int nt = 0; nt < 8; nt++) {
        int n = wn * 64 + nt * 8 + r8;
        rbB[nt] = (uint32_t)n * 128 + ((uint32_t)r8 << 4) + (uint32_t)t * 4;
    }

    // ---------- prologue ----------
    load_stage();
    load_stage();

    // ---------- mainloop ----------
    for (int i = 0; i < iters; i++) {
        cp_wait<STAGES - 2>();
        __syncthreads();
        if (fi < iters) load_stage();

        const uint32_t aslot = sbase + (uint32_t)(i % STAGES) * STAGE_BYTES;
        const uint32_t bslot = aslot + A_BYTES;

        #pragma unroll
        for (int ks = 0; ks < 4; ks++) {
            const uint32_t x0 = (uint32_t)(2 * ks) << 4;
            uint32_t af[4][4], bf[8][2];
            #pragma unroll
            for (int mt = 0; mt < 4; mt++) {
                uint32_t b0 = aslot + rbA[mt][0];
                uint32_t b1 = aslot + rbA[mt][1];
                af[mt][0] = ldtf32(b0 ^ x0);
                af[mt][1] = ldtf32(b1 ^ x0);
                af[mt][2] = ldtf32(b0 ^ (x0 | 16u));
                af[mt][3] = ldtf32(b1 ^ (x0 | 16u));
            }
            #pragma unroll
            for (int nt = 0; nt < 8; nt++) {
                uint32_t bb = bslot + rbB[nt];
                bf[nt][0] = ldtf32(bb ^ x0);
                bf[nt][1] = ldtf32(bb ^ (x0 | 16u));
            }
            #pragma unroll
            for (int mt = 0; mt < 4; mt++)
                #pragma unroll
                for (int nt = 0; nt < 8; nt++)
                    mma_tf32(acc[mt][nt], af[mt], bf[nt]);
        }
    }

    // ---------- epilogue: direct float2 stores ----------
    const int ldo = ENCODE ? F_DIM : H_DIM;
    float* ob = gOut + (size_t)z * BS_DIM * ldo;
    #pragma unroll
    for (int mt = 0; mt < 4; mt++) {
        #pragma unroll
        for (int nt = 0; nt < 8; nt++) {
            int row = m0 + wm * 64 + mt * 16 + r8;
            int col = n0 + wn * 64 + nt * 8 + t * 2;
            float v0 = acc[mt][nt][0], v1 = acc[mt][nt][1];
            float v2 = acc[mt][nt][2], v3 = acc[mt][nt][3];
            if (ENCODE) {
                v0 = fmaxf(v0, 0.0f); v1 = fmaxf(v1, 0.0f);
                v2 = fmaxf(v2, 0.0f); v3 = fmaxf(v3, 0.0f);
            }
            *(float2*)&ob[(size_t)row * ldo + col]       = make_float2(v0, v1);
            *(float2*)&ob[(size_t)(row + 8) * ldo + col] = make_float2(v2, v3);
        }
    }
}

extern "C" void kernel_launch(void* const* d_in, const int* in_sizes, int n_in,
                              void* d_out, int out_size) {
    (void)in_sizes; (void)n_in; (void)out_size;
    const float* resid = (const float*)d_in[0];   // [L, B, S, H]
    const float* enc_w = (const float*)d_in[1];   // [L, F, H]
    const float* dec_w = (const float*)d_in[2];   // [L, L, H, F]
    float* out   = (float*)d_out;
    float* feats = out;                                   // [L, BS, F]
    float* recon = out + (size_t)L_DIM * BS_DIM * F_DIM;  // [L, BS, H]

    cudaFuncSetAttribute(clt_gemm<true>,  cudaFuncAttributeMaxDynamicSharedMemorySize, SMEM_BYTES);
    cudaFuncSetAttribute(clt_gemm<false>, cudaFuncAttributeMaxDynamicSharedMemorySize, SMEM_BYTES);

    dim3 grid_enc(BS_DIM / TM, F_DIM / TN, L_DIM);   // 16 x 4 x 16
    clt_gemm<true><<<grid_enc, NTHREADS, SMEM_BYTES>>>(resid, enc_w, feats);

    dim3 grid_dec(BS_DIM / TM, H_DIM / TN, L_DIM);   // 16 x 16 x 16
    clt_gemm<false><<<grid_dec, NTHREADS, SMEM_BYTES>>>(feats, dec_w, recon);
}

// round 7
// speedup vs baseline: 2.0734x; 2.0734x over previous
// CrossLayerTranscoder — tf32 mma.sync GEMM. R7: R5's coalesced cp.async loader
// (consecutive-chunk mapping, 128B-line friendly) fused with R6's XOR fragment
// addressing + incremental pointers. R6's row-per-thread loader caused 32
// discrete 16B lines per warp instruction -> L2 47% bound; reverted.
//
// encode: feats[l] = relu(resid[l] @ enc_w[l]^T)            M=2048,N=512,K=2048
// decode: recon[t] = sum_{s<=t} feats[s] @ dec_w[s,t]^T     M=2048,N=2048,K=(t+1)*512
//
// CTA 128x128x32, 3-stage cp.async, 128 threads (2 CTAs/SM), 4 warps of 64x64.

#include <cuda_runtime.h>
#include <cstdint>
#include <cstddef>

#define L_DIM 16
#define BS_DIM 2048
#define H_DIM 2048
#define F_DIM 512

#define TM 128
#define TN 128
#define TK 32
#define STAGES 3
#define NTHREADS 128

#define A_BYTES 16384                        // TM*TK*4
#define STAGE_BYTES 32768                    // A + B
#define SMEM_BYTES (STAGES * STAGE_BYTES)    // 96 KB

__device__ __forceinline__ uint32_t smem_u32(const void* p) {
    uint32_t a;
    asm("{ .reg .u64 t; cvta.to.shared.u64 t, %1; cvt.u32.u64 %0, t; }" : "=r"(a) : "l"(p));
    return a;
}
__device__ __forceinline__ void cp_async16(uint32_t dst, const float* src) {
    asm volatile("cp.async.cg.shared.global [%0], [%1], 16;" :: "r"(dst), "l"(src));
}
__device__ __forceinline__ void cp_commit() { asm volatile("cp.async.commit_group;"); }
template <int N> __device__ __forceinline__ void cp_wait() {
    asm volatile("cp.async.wait_group %0;" :: "n"(N));
}
__device__ __forceinline__ uint32_t ldtf32(uint32_t addr) {
    float v; uint32_t r;
    asm volatile("ld.shared.f32 %0, [%1];" : "=f"(v) : "r"(addr));
    asm("cvt.rna.tf32.f32 %0, %1;" : "=r"(r) : "f"(v));
    return r;
}
__device__ __forceinline__ void mma_tf32(float* c, const uint32_t* a, const uint32_t* b) {
    asm volatile(
        "mma.sync.aligned.m16n8k8.row.col.f32.tf32.tf32.f32 "
        "{%0,%1,%2,%3}, {%4,%5,%6,%7}, {%8,%9}, {%0,%1,%2,%3};"
        : "+f"(c[0]), "+f"(c[1]), "+f"(c[2]), "+f"(c[3])
        : "r"(a[0]), "r"(a[1]), "r"(a[2]), "r"(a[3]), "r"(b[0]), "r"(b[1]));
}

// SMEM tile layout: row-major 32 floats/row; chunk = (k>>2) ^ (row&7), word = k&3.
// Fragment address: rowbase ^ ((2ks)<<4), k+4 variant ^16 (row&7 == r8 for all
// fragment rows).
//
// Loader mapping: chunk q = j*128 + tid, j=0..7 per tile. row = j*16 + (tid>>3),
// c = tid&7. Lanes of a warp cover 4 consecutive rows x 8 chunks -> whole 128B
// lines. row&7 = (tid>>3)&7 is per-thread constant, so smem dst = dst0 + j*2048
// and global src = p + j*16*ld with compile-time ld.

template <bool ENCODE>
__global__ __launch_bounds__(NTHREADS, 2)
void clt_gemm(const float* __restrict__ gA, const float* __restrict__ gB,
              float* __restrict__ gOut) {
    extern __shared__ float smem[];
    const uint32_t sbase = smem_u32(smem);
    const int tid  = threadIdx.x;
    const int lane = tid & 31;
    const int w    = tid >> 5;
    const int wm   = w & 1;        // 2 warps along M (64 rows)
    const int wn   = w >> 1;       // 2 warps along N (64 cols)
    const int r8   = lane >> 2;
    const int t    = lane & 3;
    const int m0   = blockIdx.x * TM;
    const int n0   = blockIdx.y * TN;
    const int z    = (int)gridDim.z - 1 - (int)blockIdx.z;   // heavy z first
    const int iters = ENCODE ? (H_DIM / TK) : ((z + 1) * (F_DIM / TK));
    const int LD   = ENCODE ? H_DIM : F_DIM;   // compile-time row pitch

    float acc[4][8][4];
    #pragma unroll
    for (int mt = 0; mt < 4; mt++)
        #pragma unroll
        for (int nt = 0; nt < 8; nt++)
            #pragma unroll
            for (int r = 0; r < 4; r++) acc[mt][nt][r] = 0.0f;

    // ---------- producer pointers (incremental) ----------
    const int tid8 = tid >> 3;       // 0..15: base row within 16-row group
    const int cch  = tid & 7;        // chunk column
    const float* pA;
    const float* pB;
    if (ENCODE) {
        pA = gA + ((size_t)z * BS_DIM + m0 + tid8) * H_DIM + cch * 4;
        pB = gB + ((size_t)z * F_DIM + n0 + tid8) * H_DIM + cch * 4;
    } else {
        pA = gA + (size_t)(m0 + tid8) * F_DIM + cch * 4;               // feats[0]
        pB = gB + ((size_t)z * H_DIM + n0 + tid8) * F_DIM + cch * 4;   // dec_w[0][z]
    }
    const uint32_t dst0 = (uint32_t)tid8 * 128 + ((uint32_t)(cch ^ (tid8 & 7)) << 4);
    int fi = 0;
    auto load_stage = [&]() {
        const int slot = fi % STAGES;
        uint32_t dA = sbase + (uint32_t)slot * STAGE_BYTES + dst0;
        uint32_t dB = dA + A_BYTES;
        #pragma unroll
        for (int j = 0; j < 8; j++)
            cp_async16(dA + (uint32_t)j * 2048, pA + (size_t)j * 16 * LD);
        #pragma unroll
        for (int j = 0; j < 8; j++)
            cp_async16(dB + (uint32_t)j * 2048, pB + (size_t)j * 16 * LD);
        cp_commit();
        if (ENCODE) { pA += TK; pB += TK; }
        else {
            bool roll = (fi & 15) == 15;   // advance source layer s
            pA += roll ? ((size_t)BS_DIM * F_DIM - 15 * TK) : TK;
            pB += roll ? ((size_t)L_DIM * H_DIM * F_DIM - 15 * TK) : TK;
        }
        fi++;
    };

    // ---------- consumer rowbase offsets (bytes within tile) ----------
    uint32_t rbA[4][2], rbB[8];
    #pragma unroll
    for (int mt = 0; mt < 4; mt++) {
        int r = wm * 64 + mt * 16 + r8;
        rbA[mt][0] = (uint32_t)r * 128 + ((uint32_t)r8 << 4) + (uint32_t)t * 4;
        rbA[mt][1] = rbA[mt][0] + 8 * 128;
    }
    #pragma unroll
    for (int nt = 0; nt < 8; nt++) {
        int n = wn * 64 + nt * 8 + r8;
        rbB[nt] = (uint32_t)n * 128 + ((uint32_t)r8 << 4) + (uint32_t)t * 4;
    }

    // ---------- prologue ----------
    load_stage();
    load_stage();

    // ---------- mainloop: one barrier per iteration ----------
    for (int i = 0; i < iters; i++) {
        cp_wait<STAGES - 2>();
        __syncthreads();
        if (fi < iters) load_stage();

        const uint32_t aslot = sbase + (uint32_t)(i % STAGES) * STAGE_BYTES;
        const uint32_t bslot = aslot + A_BYTES;

        #pragma unroll
        for (int ks = 0; ks < 4; ks++) {
            const uint32_t x0 = (uint32_t)(2 * ks) << 4;
            uint32_t af[4][4], bf[8][2];
            #pragma unroll
            for (int mt = 0; mt < 4; mt++) {
                uint32_t b0 = aslot + rbA[mt][0];
                uint32_t b1 = aslot + rbA[mt][1];
                af[mt][0] = ldtf32(b0 ^ x0);
                af[mt][1] = ldtf32(b1 ^ x0);
                af[mt][2] = ldtf32(b0 ^ (x0 | 16u));
                af[mt][3] = ldtf32(b1 ^ (x0 | 16u));
            }
            #pragma unroll
            for (int nt = 0; nt < 8; nt++) {
                uint32_t bb = bslot + rbB[nt];
                bf[nt][0] = ldtf32(bb ^ x0);
                bf[nt][1] = ldtf32(bb ^ (x0 | 16u));
            }
            #pragma unroll
            for (int mt = 0; mt < 4; mt++)
                #pragma unroll
                for (int nt = 0; nt < 8; nt++)
                    mma_tf32(acc[mt][nt], af[mt], bf[nt]);
        }
    }

    // ---------- epilogue: direct float2 stores ----------
    const int ldo = ENCODE ? F_DIM : H_DIM;
    float* ob = gOut + (size_t)z * BS_DIM * ldo;
    #pragma unroll
    for (int mt = 0; mt < 4; mt++) {
        #pragma unroll
        for (int nt = 0; nt < 8; nt++) {
            int row = m0 + wm * 64 + mt * 16 + r8;
            int col = n0 + wn * 64 + nt * 8 + t * 2;
            float v0 = acc[mt][nt][0], v1 = acc[mt][nt][1];
            float v2 = acc[mt][nt][2], v3 = acc[mt][nt][3];
            if (ENCODE) {
                v0 = fmaxf(v0, 0.0f); v1 = fmaxf(v1, 0.0f);
                v2 = fmaxf(v2, 0.0f); v3 = fmaxf(v3, 0.0f);
            }
            *(float2*)&ob[(size_t)row * ldo + col]       = make_float2(v0, v1);
            *(float2*)&ob[(size_t)(row + 8) * ldo + col] = make_float2(v2, v3);
        }
    }
}

extern "C" void kernel_launch(void* const* d_in, const int* in_sizes, int n_in,
                              void* d_out, int out_size) {
    (void)in_sizes; (void)n_in; (void)out_size;
    const float* resid = (const float*)d_in[0];   // [L, B, S, H]
    const float* enc_w = (const float*)d_in[1];   // [L, F, H]
    const float* dec_w = (const float*)d_in[2];   // [L, L, H, F]
    float* out   = (float*)d_out;
    float* feats = out;                                   // [L, BS, F]
    float* recon = out + (size_t)L_DIM * BS_DIM * F_DIM;  // [L, BS, H]

    cudaFuncSetAttribute(clt_gemm<true>,  cudaFuncAttributeMaxDynamicSharedMemorySize, SMEM_BYTES);
    cudaFuncSetAttribute(clt_gemm<false>, cudaFuncAttributeMaxDynamicSharedMemorySize, SMEM_BYTES);

    dim3 grid_enc(BS_DIM / TM, F_DIM / TN, L_DIM);   // 16 x 4 x 16
    clt_gemm<true><<<grid_enc, NTHREADS, SMEM_BYTES>>>(resid, enc_w, feats);

    dim3 grid_dec(BS_DIM / TM, H_DIM / TN, L_DIM);   // 16 x 16 x 16
    clt_gemm<false><<<grid_dec, NTHREADS, SMEM_BYTES>>>(feats, dec_w, recon);
}

// round 8
// speedup vs baseline: 2.0841x; 1.0052x over previous
// CrossLayerTranscoder — tf32 mma.sync GEMM. R8: ks-level fragment double
// buffering (hide 29-cyc LDS latency under MMA stream) + per-iter hoisted
// fragment addresses (kill redundant IADDs; alu was 34%). R7 = 3277us @ tensor 66%.
//
// encode: feats[l] = relu(resid[l] @ enc_w[l]^T)            M=2048,N=512,K=2048
// decode: recon[t] = sum_{s<=t} feats[s] @ dec_w[s,t]^T     M=2048,N=2048,K=(t+1)*512
//
// CTA 128x128x32, 3-stage cp.async, 128 threads (2 CTAs/SM), 4 warps of 64x64.

#include <cuda_runtime.h>
#include <cstdint>
#include <cstddef>

#define L_DIM 16
#define BS_DIM 2048
#define H_DIM 2048
#define F_DIM 512

#define TM 128
#define TN 128
#define TK 32
#define STAGES 3
#define NTHREADS 128

#define A_BYTES 16384                        // TM*TK*4
#define STAGE_BYTES 32768                    // A + B
#define SMEM_BYTES (STAGES * STAGE_BYTES)    // 96 KB

__device__ __forceinline__ uint32_t smem_u32(const void* p) {
    uint32_t a;
    asm("{ .reg .u64 t; cvta.to.shared.u64 t, %1; cvt.u32.u64 %0, t; }" : "=r"(a) : "l"(p));
    return a;
}
__device__ __forceinline__ void cp_async16(uint32_t dst, const float* src) {
    asm volatile("cp.async.cg.shared.global [%0], [%1], 16;" :: "r"(dst), "l"(src));
}
__device__ __forceinline__ void cp_commit() { asm volatile("cp.async.commit_group;"); }
template <int N> __device__ __forceinline__ void cp_wait() {
    asm volatile("cp.async.wait_group %0;" :: "n"(N));
}
__device__ __forceinline__ uint32_t ldtf32(uint32_t addr) {
    float v; uint32_t r;
    asm volatile("ld.shared.f32 %0, [%1];" : "=f"(v) : "r"(addr));
    asm("cvt.rna.tf32.f32 %0, %1;" : "=r"(r) : "f"(v));
    return r;
}
__device__ __forceinline__ void mma_tf32(float* c, const uint32_t* a, const uint32_t* b) {
    asm volatile(
        "mma.sync.aligned.m16n8k8.row.col.f32.tf32.tf32.f32 "
        "{%0,%1,%2,%3}, {%4,%5,%6,%7}, {%8,%9}, {%0,%1,%2,%3};"
        : "+f"(c[0]), "+f"(c[1]), "+f"(c[2]), "+f"(c[3])
        : "r"(a[0]), "r"(a[1]), "r"(a[2]), "r"(a[3]), "r"(b[0]), "r"(b[1]));
}

// SMEM tile layout: row-major 32 floats/row; chunk = (k>>2) ^ (row&7), word = k&3.
// Fragment address: (slotbase + rowbase) ^ ((2ks)<<4); k+4 variant additionally ^16.
// (row&7 == r8 for every fragment row, so the XOR form is exact.)

template <bool ENCODE>
__global__ __launch_bounds__(NTHREADS, 2)
void clt_gemm(const float* __restrict__ gA, const float* __restrict__ gB,
              float* __restrict__ gOut) {
    extern __shared__ float smem[];
    const uint32_t sbase = smem_u32(smem);
    const int tid  = threadIdx.x;
    const int lane = tid & 31;
    const int w    = tid >> 5;
    const int wm   = w & 1;        // 2 warps along M (64 rows)
    const int wn   = w >> 1;       // 2 warps along N (64 cols)
    const int r8   = lane >> 2;
    const int t    = lane & 3;
    const int m0   = blockIdx.x * TM;
    const int n0   = blockIdx.y * TN;
    const int z    = (int)gridDim.z - 1 - (int)blockIdx.z;   // heavy z first
    const int iters = ENCODE ? (H_DIM / TK) : ((z + 1) * (F_DIM / TK));
    const int LD   = ENCODE ? H_DIM : F_DIM;   // compile-time row pitch

    float acc[4][8][4];
    #pragma unroll
    for (int mt = 0; mt < 4; mt++)
        #pragma unroll
        for (int nt = 0; nt < 8; nt++)
            #pragma unroll
            for (int r = 0; r < 4; r++) acc[mt][nt][r] = 0.0f;

    // ---------- producer pointers (incremental, coalesced mapping) ----------
    const int tid8 = tid >> 3;       // 0..15: base row within 16-row group
    const int cch  = tid & 7;        // chunk column
    const float* pA;
    const float* pB;
    if (ENCODE) {
        pA = gA + ((size_t)z * BS_DIM + m0 + tid8) * H_DIM + cch * 4;
        pB = gB + ((size_t)z * F_DIM + n0 + tid8) * H_DIM + cch * 4;
    } else {
        pA = gA + (size_t)(m0 + tid8) * F_DIM + cch * 4;               // feats[0]
        pB = gB + ((size_t)z * H_DIM + n0 + tid8) * F_DIM + cch * 4;   // dec_w[0][z]
    }
    const uint32_t dst0 = (uint32_t)tid8 * 128 + ((uint32_t)(cch ^ (tid8 & 7)) << 4);
    int fi = 0;
    auto load_stage = [&]() {
        const int slot = fi % STAGES;
        uint32_t dA = sbase + (uint32_t)slot * STAGE_BYTES + dst0;
        uint32_t dB = dA + A_BYTES;
        #pragma unroll
        for (int j = 0; j < 8; j++)
            cp_async16(dA + (uint32_t)j * 2048, pA + (size_t)j * 16 * LD);
        #pragma unroll
        for (int j = 0; j < 8; j++)
            cp_async16(dB + (uint32_t)j * 2048, pB + (size_t)j * 16 * LD);
        cp_commit();
        if (ENCODE) { pA += TK; pB += TK; }
        else {
            bool roll = (fi & 15) == 15;   // advance source layer s
            pA += roll ? ((size_t)BS_DIM * F_DIM - 15 * TK) : TK;
            pB += roll ? ((size_t)L_DIM * H_DIM * F_DIM - 15 * TK) : TK;
        }
        fi++;
    };

    // ---------- consumer rowbase offsets (bytes within tile) ----------
    uint32_t rbA[4][2], rbB[8];
    #pragma unroll
    for (int mt = 0; mt < 4; mt++) {
        int r = wm * 64 + mt * 16 + r8;
        rbA[mt][0] = (uint32_t)r * 128 + ((uint32_t)r8 << 4) + (uint32_t)t * 4;
        rbA[mt][1] = rbA[mt][0] + 8 * 128;
    }
    #pragma unroll
    for (int nt = 0; nt < 8; nt++) {
        int n = wn * 64 + nt * 8 + r8;
        rbB[nt] = (uint32_t)n * 128 + ((uint32_t)r8 << 4) + (uint32_t)t * 4;
    }

    // ---------- prologue ----------
    load_stage();
    load_stage();

    // ---------- mainloop: ks-pipelined fragments, one barrier per iter ----------
    uint32_t af[2][4][4], bf[2][8][2];
    for (int i = 0; i < iters; i++) {
        cp_wait<STAGES - 2>();
        __syncthreads();
        if (fi < iters) load_stage();

        const uint32_t aslot = sbase + (uint32_t)(i % STAGES) * STAGE_BYTES;
        const uint32_t bslot = aslot + A_BYTES;

        // hoist absolute fragment base addresses for this stage
        uint32_t aaddr[4][2], baddr[8];
        #pragma unroll
        for (int mt = 0; mt < 4; mt++) {
            aaddr[mt][0] = aslot + rbA[mt][0];
            aaddr[mt][1] = aslot + rbA[mt][1];
        }
        #pragma unroll
        for (int nt = 0; nt < 8; nt++) baddr[nt] = bslot + rbB[nt];

        // fragment loader for k-step ks into buffer cb
        auto ldfrag = [&](int ks, int cb) {
            const uint32_t x0 = (uint32_t)(2 * ks) << 4;
            const uint32_t x1 = x0 | 16u;
            #pragma unroll
            for (int mt = 0; mt < 4; mt++) {
                af[cb][mt][0] = ldtf32(aaddr[mt][0] ^ x0);
                af[cb][mt][1] = ldtf32(aaddr[mt][1] ^ x0);
                af[cb][mt][2] = ldtf32(aaddr[mt][0] ^ x1);
                af[cb][mt][3] = ldtf32(aaddr[mt][1] ^ x1);
            }
            #pragma unroll
            for (int nt = 0; nt < 8; nt++) {
                bf[cb][nt][0] = ldtf32(baddr[nt] ^ x0);
                bf[cb][nt][1] = ldtf32(baddr[nt] ^ x1);
            }
        };

        ldfrag(0, 0);
        #pragma unroll
        for (int ks = 0; ks < 4; ks++) {
            const int cb = ks & 1;
            if (ks < 3) ldfrag(ks + 1, cb ^ 1);
            #pragma unroll
            for (int mt = 0; mt < 4; mt++)
                #pragma unroll
                for (int nt = 0; nt < 8; nt++)
                    mma_tf32(acc[mt][nt], af[cb][mt], bf[cb][nt]);
        }
    }

    // ---------- epilogue: direct float2 stores ----------
    const int ldo = ENCODE ? F_DIM : H_DIM;
    float* ob = gOut + (size_t)z * BS_DIM * ldo;
    #pragma unroll
    for (int mt = 0; mt < 4; mt++) {
        #pragma unroll
        for (int nt = 0; nt < 8; nt++) {
            int row = m0 + wm * 64 + mt * 16 + r8;
            int col = n0 + wn * 64 + nt * 8 + t * 2;
            float v0 = acc[mt][nt][0], v1 = acc[mt][nt][1];
            float v2 = acc[mt][nt][2], v3 = acc[mt][nt][3];
            if (ENCODE) {
                v0 = fmaxf(v0, 0.0f); v1 = fmaxf(v1, 0.0f);
                v2 = fmaxf(v2, 0.0f); v3 = fmaxf(v3, 0.0f);
            }
            *(float2*)&ob[(size_t)row * ldo + col]       = make_float2(v0, v1);
            *(float2*)&ob[(size_t)(row + 8) * ldo + col] = make_float2(v2, v3);
        }
    }
}

extern "C" void kernel_launch(void* const* d_in, const int* in_sizes, int n_in,
                              void* d_out, int out_size) {
    (void)in_sizes; (void)n_in; (void)out_size;
    const float* resid = (const float*)d_in[0];   // [L, B, S, H]
    const float* enc_w = (const float*)d_in[1];   // [L, F, H]
    const float* dec_w = (const float*)d_in[2];   // [L, L, H, F]
    float* out   = (float*)d_out;
    float* feats = out;                                   // [L, BS, F]
    float* recon = out + (size_t)L_DIM * BS_DIM * F_DIM;  // [L, BS, H]

    cudaFuncSetAttribute(clt_gemm<true>,  cudaFuncAttributeMaxDynamicSharedMemorySize, SMEM_BYTES);
    cudaFuncSetAttribute(clt_gemm<false>, cudaFuncAttributeMaxDynamicSharedMemorySize, SMEM_BYTES);

    dim3 grid_enc(BS_DIM / TM, F_DIM / TN, L_DIM);   // 16 x 4 x 16
    clt_gemm<true><<<grid_enc, NTHREADS, SMEM_BYTES>>>(resid, enc_w, feats);

    dim3 grid_dec(BS_DIM / TM, H_DIM / TN, L_DIM);   // 16 x 16 x 16
    clt_gemm<false><<<grid_dec, NTHREADS, SMEM_BYTES>>>(feats, dec_w, recon);
}